// round 8
// baseline (speedup 1.0000x reference)
#include <cuda_runtime.h>

#define BATCH        16384
#define NUM_FIELDS   20
#define NUM_FEATURES 100000
#define LATENT_DIM   64

// Two samples per warp (one per half-warp); each lane owns 4 of 64 dims ->
// LDG.128 per embedding row; 8192 warps (~55/SM, single-ish wave).
// Gathers issued as FOUR groups of 5 with scheduling barriers between them:
// MLP_p1 20 -> 5 pushes the cross-CTA L1tex wavefront-queue contention term
// (spr ~ oe*MLP_p1 vs Q_th=16) essentially to the floor, and keeps the live
// register high-water mark low (occ ~89%).
__global__ __launch_bounds__(256)
void ffm_kernel(const int* __restrict__ x,
                const float* __restrict__ emb,
                float* __restrict__ out)
{
    const int gwarp = (blockIdx.x * blockDim.x + threadIdx.x) >> 5;
    const int lane  = threadIdx.x & 31;
    const int half  = lane >> 4;          // sample within the warp
    const int lh    = lane & 15;          // lane within half-warp
    const int s     = gwarp * 2 + half;   // batch sample id
    if (s >= BATCH) return;

    // 20 indices per half-warp: lanes 0..15 hold fields 0..15,
    // lanes 0..3 additionally hold fields 16..19.
    const int* xrow = x + s * NUM_FIELDS;
    int xi0 = __ldg(xrow + lh);                                    // fields 0..15
    int xi1 = (lh < NUM_FIELDS - 16) ? __ldg(xrow + 16 + lh) : 0;  // fields 16..19

    float4 sv = make_float4(0.f, 0.f, 0.f, 0.f);   // partial of sum_f V[f]
    float  sq = 0.f;                               // partial of sum V^2

    #pragma unroll
    for (int g = 0; g < NUM_FIELDS; g += 5) {
        float4 buf[5];
        #pragma unroll
        for (int j = 0; j < 5; ++j) {
            const int f = g + j;
            int idx;
            if (f < 16) idx = __shfl_sync(0xffffffffu, xi0, f, 16);
            else        idx = __shfl_sync(0xffffffffu, xi1, f - 16, 16);
            const float4* row = reinterpret_cast<const float4*>(
                emb + ((size_t)f * NUM_FEATURES + (size_t)idx) * LATENT_DIM);
            buf[j] = __ldg(row + lh);
        }
        #pragma unroll
        for (int j = 0; j < 5; ++j) {
            const float4 v = buf[j];
            sv.x += v.x;  sv.y += v.y;  sv.z += v.z;  sv.w += v.w;
            sq = fmaf(v.x, v.x, sq);  sq = fmaf(v.y, v.y, sq);
            sq = fmaf(v.z, v.z, sq);  sq = fmaf(v.w, v.w, sq);
        }
        // Keep the next group's LDGs from being hoisted into this burst.
        asm volatile("" ::: "memory");
    }

    float part = fmaf(sv.x, sv.x, fmaf(sv.y, sv.y,
                 fmaf(sv.z, sv.z, sv.w * sv.w))) - sq;
    int   lin  = xi0 + xi1;

    // Reduce within the 16-lane half-warp.
    #pragma unroll
    for (int o = 8; o > 0; o >>= 1) {
        part += __shfl_xor_sync(0xffffffffu, part, o);
        lin  += __shfl_xor_sync(0xffffffffu, lin,  o);
    }

    if (lh == 0)
        out[s] = (float)lin + 0.5f * part;
}

extern "C" void kernel_launch(void* const* d_in, const int* in_sizes, int n_in,
                              void* d_out, int out_size)
{
    const int*   x   = (const int*)d_in[0];     // (16384, 20) int32
    // d_in[1] = field_indices (arange(20)) — identity, unused
    const float* emb = (const float*)d_in[2];   // (20, 100000, 64) fp32
    float*       out = (float*)d_out;           // (16384,) fp32

    const int threads = 256;                    // 8 warps = 16 samples / block
    const int warps   = (BATCH + 1) / 2;        // 8192 warps
    const int blocks  = (warps * 32 + threads - 1) / threads;  // 1024
    ffm_kernel<<<blocks, threads>>>(x, emb, out);
}